// round 3
// baseline (speedup 1.0000x reference)
#include <cuda_runtime.h>
#include <cuda_bf16.h>

#define NNODES 50000
#define NEDGES 800000
#define NGRAPHS 512
#define HID 128
#define NCLS 10

// ---------------- scratch (device globals; no allocs allowed) ----------------
__device__ float g_deg_in[NNODES];
__device__ float g_norm_src[NNODES];
__device__ float g_norm_dst[NNODES];
__device__ float g_agg0[NNODES];
__device__ float g_ha[(size_t)NNODES * HID];   // h (scaled by norm_src when feeding a scatter)
__device__ float g_hb[(size_t)NNODES * HID];
__device__ float g_aggA[(size_t)NNODES * HID];
__device__ float g_aggB[(size_t)NNODES * HID];
__device__ float g_hg[NGRAPHS * HID];
__device__ float g_cnt[NGRAPHS];
__device__ float g_deg_out[NNODES];

// vector reduction: 16B fp32 add (PTX ISA 8.1+, sm_90a+)
__device__ __forceinline__ void red_add_v4(float* addr, float4 v) {
#if __CUDA_ARCH__ >= 900
    asm volatile("red.global.add.v4.f32 [%0], {%1,%2,%3,%4};"
                 :: "l"(addr), "f"(v.x), "f"(v.y), "f"(v.z), "f"(v.w) : "memory");
#else
    atomicAdd(addr + 0, v.x);
    atomicAdd(addr + 1, v.y);
    atomicAdd(addr + 2, v.z);
    atomicAdd(addr + 3, v.w);
#endif
}

// ---------------- zero everything that gets accumulated ----------------
__global__ __launch_bounds__(256) void zero_kernel() {
    size_t i = (size_t)blockIdx.x * blockDim.x + threadIdx.x;
    if (i < (size_t)NNODES * HID) { g_aggA[i] = 0.f; g_aggB[i] = 0.f; }
    if (i < NNODES) { g_deg_in[i] = 0.f; g_deg_out[i] = 0.f; g_agg0[i] = 0.f; }
    if (i < NGRAPHS * HID) g_hg[i] = 0.f;
    if (i < NGRAPHS) g_cnt[i] = 0.f;
}

// ---------------- degree histograms ----------------
__global__ __launch_bounds__(256) void degree_kernel(const int* __restrict__ src,
                                                     const int* __restrict__ dst) {
    int e = blockIdx.x * blockDim.x + threadIdx.x;
    if (e < NEDGES) {
        atomicAdd(&g_deg_out[src[e]], 1.0f);
        atomicAdd(&g_deg_in[dst[e]], 1.0f);
    }
}

// ---------------- norms ----------------
__global__ __launch_bounds__(256) void norm_kernel() {
    int i = blockIdx.x * blockDim.x + threadIdx.x;
    if (i < NNODES) {
        g_norm_src[i] = rsqrtf(fmaxf(g_deg_out[i], 1.0f));
        g_norm_dst[i] = rsqrtf(fmaxf(g_deg_in[i], 1.0f));
    }
}

// ---------------- layer 0 scatter: scalar feature (h0 = in_deg) ----------------
__global__ __launch_bounds__(256) void scatter0_kernel(const int* __restrict__ src,
                                                       const int* __restrict__ dst) {
    int e = blockIdx.x * blockDim.x + threadIdx.x;
    if (e < NEDGES) {
        int s = src[e];
        atomicAdd(&g_agg0[dst[e]], g_deg_in[s] * g_norm_src[s]);
    }
}

// ---------------- layer 0 dense: ha = relu(agg0*norm_dst * W0 + b0) * norm_src ----
__global__ __launch_bounds__(256) void dense0_kernel(const float* __restrict__ W0,
                                                     const float* __restrict__ b0) {
    size_t idx = (size_t)blockIdx.x * blockDim.x + threadIdx.x;
    if (idx < (size_t)NNODES * HID) {
        int i = (int)(idx >> 7);
        int c = (int)(idx & 127);
        float a = g_agg0[i] * g_norm_dst[i];
        g_ha[idx] = fmaxf(a * __ldg(&W0[c]) + __ldg(&b0[c]), 0.0f) * g_norm_src[i];
    }
}

// ---------------- edge scatter: one warp/edge, lane owns 4 contiguous floats ----
// PHASE 0: g_ha -> g_aggA     PHASE 1: g_hb -> g_aggB
template <int PHASE>
__global__ __launch_bounds__(256) void scatter_kernel(const int* __restrict__ src,
                                                      const int* __restrict__ dst) {
    const float* __restrict__ h = (PHASE == 0) ? g_ha : g_hb;
    float* __restrict__ agg = (PHASE == 0) ? g_aggA : g_aggB;
    int warp = (blockIdx.x * blockDim.x + threadIdx.x) >> 5;
    int lane = threadIdx.x & 31;
    if (warp >= NEDGES) return;
    int s = __ldg(&src[warp]);
    int d = __ldg(&dst[warp]);
    float4 v = *(const float4*)(h + (size_t)s * HID + lane * 4);
    red_add_v4(agg + (size_t)d * HID + lane * 4, v);
}

// ---------------- GEMM: out = relu((agg*norm_dst) @ W + b) [*norm_src] ----------
// PHASE 0: g_aggA -> g_hb (scaled by norm_src)   PHASE 1: g_aggB -> g_ha (unscaled)
template <int PHASE>
__global__ __launch_bounds__(256) void gemm_relu_kernel(const float* __restrict__ W,
                                                        const float* __restrict__ bias) {
    const float* __restrict__ A = (PHASE == 0) ? g_aggA : g_aggB;
    float* __restrict__ O = (PHASE == 0) ? g_hb : g_ha;

    __shared__ float Ws[32 * HID];      // [kk][c]
    __shared__ float As[64 * 33];       // [r][kk], padded

    int t = threadIdx.x;
    int cg = t & 15;    // 16 col groups * 8 cols
    int rg = t >> 4;    // 16 row groups * 4 rows
    int row0 = blockIdx.x * 64;

    float acc[4][8];
#pragma unroll
    for (int r = 0; r < 4; r++)
#pragma unroll
        for (int j = 0; j < 8; j++) acc[r][j] = 0.f;

    for (int k0 = 0; k0 < HID; k0 += 32) {
#pragma unroll
        for (int i = 0; i < 16; i++) {
            int idx = t + i * 256;                 // kk*128 + c
            Ws[idx] = W[(size_t)(k0 + (idx >> 7)) * HID + (idx & 127)];
        }
#pragma unroll
        for (int i = 0; i < 8; i++) {
            int idx = t + i * 256;                 // r*32 + kk
            int r = idx >> 5, kk = idx & 31;
            int row = row0 + r;
            float v = 0.f;
            if (row < NNODES) v = A[(size_t)row * HID + k0 + kk] * g_norm_dst[row];
            As[r * 33 + kk] = v;
        }
        __syncthreads();
#pragma unroll
        for (int kk = 0; kk < 32; kk++) {
            float a0 = As[(rg * 4 + 0) * 33 + kk];
            float a1 = As[(rg * 4 + 1) * 33 + kk];
            float a2 = As[(rg * 4 + 2) * 33 + kk];
            float a3 = As[(rg * 4 + 3) * 33 + kk];
            float4 w0 = *(const float4*)&Ws[kk * HID + cg * 8];
            float4 w1 = *(const float4*)&Ws[kk * HID + cg * 8 + 4];
            float w[8] = {w0.x, w0.y, w0.z, w0.w, w1.x, w1.y, w1.z, w1.w};
#pragma unroll
            for (int j = 0; j < 8; j++) {
                acc[0][j] += a0 * w[j];
                acc[1][j] += a1 * w[j];
                acc[2][j] += a2 * w[j];
                acc[3][j] += a3 * w[j];
            }
        }
        __syncthreads();
    }
#pragma unroll
    for (int r = 0; r < 4; r++) {
        int row = row0 + rg * 4 + r;
        if (row < NNODES) {
            float sc = (PHASE == 0) ? g_norm_src[row] : 1.0f;
#pragma unroll
            for (int j = 0; j < 8; j++) {
                int c = cg * 8 + j;
                O[(size_t)row * HID + c] = fmaxf(acc[r][j] + __ldg(&bias[c]), 0.0f) * sc;
            }
        }
    }
}

// ---------------- pooling: segmented sum, graph_ids sorted, float4 lanes ------
__global__ __launch_bounds__(128) void pool_kernel(const int* __restrict__ gid) {
    const float4* __restrict__ h4 = (const float4*)g_ha;   // 32 float4 per row
    int q = threadIdx.x & 31;        // float4 slot 0..31
    int sub = threadIdx.x >> 5;      // 4 row-subsets per block
    int n0 = blockIdx.x * 64 + sub * 16;
    int nend = n0 + 16;
    if (nend > NNODES) nend = NNODES;
    if (n0 >= NNODES) return;
    float4 acc = make_float4(0.f, 0.f, 0.f, 0.f);
    int cacc = 0;
    int cur = __ldg(&gid[n0]);
    for (int n = n0; n < nend; n++) {
        int g = __ldg(&gid[n]);
        if (g != cur) {
            red_add_v4(&g_hg[cur * HID + q * 4], acc);
            if (q == 0) atomicAdd(&g_cnt[cur], (float)cacc);
            acc = make_float4(0.f, 0.f, 0.f, 0.f); cacc = 0; cur = g;
        }
        float4 v = h4[(size_t)n * 32 + q];
        acc.x += v.x; acc.y += v.y; acc.z += v.z; acc.w += v.w;
        cacc++;
    }
    red_add_v4(&g_hg[cur * HID + q * 4], acc);
    if (q == 0) atomicAdd(&g_cnt[cur], (float)cacc);
}

// ---------------- classifier: out = (hg/cnt) @ Wc + bc ----------------
__global__ __launch_bounds__(256) void cls_kernel(const float* __restrict__ Wc,
                                                  const float* __restrict__ bc,
                                                  float* __restrict__ out) {
    int g = blockIdx.x * (blockDim.x >> 5) + (threadIdx.x >> 5);
    int lane = threadIdx.x & 31;
    if (g >= NGRAPHS) return;
    float inv = 1.0f / fmaxf(g_cnt[g], 1.0f);
    float x[4];
#pragma unroll
    for (int j = 0; j < 4; j++) x[j] = g_hg[g * HID + lane + j * 32] * inv;
#pragma unroll
    for (int cls = 0; cls < NCLS; cls++) {
        float p = 0.f;
#pragma unroll
        for (int j = 0; j < 4; j++) p += x[j] * __ldg(&Wc[(lane + j * 32) * NCLS + cls]);
#pragma unroll
        for (int o = 16; o; o >>= 1) p += __shfl_xor_sync(0xffffffffu, p, o);
        if (lane == 0) out[g * NCLS + cls] = p + __ldg(&bc[cls]);
    }
}

// ---------------- launch ----------------
extern "C" void kernel_launch(void* const* d_in, const int* in_sizes, int n_in,
                              void* d_out, int out_size) {
    const float* W0 = (const float*)d_in[0];
    const float* b0 = (const float*)d_in[1];
    const float* W1 = (const float*)d_in[2];
    const float* b1 = (const float*)d_in[3];
    const float* W2 = (const float*)d_in[4];
    const float* b2 = (const float*)d_in[5];
    const float* Wc = (const float*)d_in[6];
    const float* bc = (const float*)d_in[7];
    const int* src = (const int*)d_in[8];
    const int* dst = (const int*)d_in[9];
    const int* gid = (const int*)d_in[10];
    float* out = (float*)d_out;

    const int ZB = ((size_t)NNODES * HID + 255) / 256;          // 25000
    const int EB = (NEDGES + 255) / 256;                        // 3125
    const int NB = (NNODES + 255) / 256;
    const int DB = ((size_t)NNODES * HID + 255) / 256;
    const int SB = (NEDGES * 32 + 255) / 256;                   // one warp per edge
    const int GB = (NNODES + 63) / 64;                          // 782

    zero_kernel<<<ZB, 256>>>();
    degree_kernel<<<EB, 256>>>(src, dst);
    norm_kernel<<<NB, 256>>>();
    scatter0_kernel<<<EB, 256>>>(src, dst);
    dense0_kernel<<<DB, 256>>>(W0, b0);

    scatter_kernel<0><<<SB, 256>>>(src, dst);
    gemm_relu_kernel<0><<<GB, 256>>>(W1, b1);

    scatter_kernel<1><<<SB, 256>>>(src, dst);
    gemm_relu_kernel<1><<<GB, 256>>>(W2, b2);

    pool_kernel<<<GB, 128>>>(gid);
    cls_kernel<<<(NGRAPHS + 7) / 8, 256>>>(Wc, bc, out);
}

// round 5
// speedup vs baseline: 1.2980x; 1.2980x over previous
#include <cuda_runtime.h>
#include <cuda_bf16.h>

#define NNODES 50000
#define NEDGES 800000
#define NGRAPHS 512
#define HID 128
#define NCLS 10

// ---------------- scratch (device globals; no allocs allowed) ----------------
__device__ float g_deg_in[NNODES];
__device__ float g_deg_out[NNODES];
__device__ float g_norm_src[NNODES];
__device__ float g_norm_dst[NNODES];
__device__ float g_ha[(size_t)NNODES * HID];   // h (pre-scaled by norm_src when feeding a gather)
__device__ float g_hb[(size_t)NNODES * HID];
__device__ float g_aggA[(size_t)NNODES * HID];
__device__ float g_aggB[(size_t)NNODES * HID];
__device__ float g_hg[NGRAPHS * HID];
__device__ float g_cnt[NGRAPHS];
// CSR by destination
__device__ int g_off[NNODES + 1];
__device__ int g_cursor[NNODES];
__device__ int g_eidx[NEDGES];                 // src node id per CSR slot

__device__ __forceinline__ void red_add_v4(float* addr, float4 v) {
    asm volatile("red.global.add.v4.f32 [%0], {%1,%2,%3,%4};"
                 :: "l"(addr), "f"(v.x), "f"(v.y), "f"(v.z), "f"(v.w) : "memory");
}

// ---------------- zero all accumulated state (NGRAPHS*HID = 65536 threads) ----
__global__ __launch_bounds__(256) void zero_kernel() {
    int i = blockIdx.x * blockDim.x + threadIdx.x;     // 0..65535
    if (i < NNODES) { g_deg_in[i] = 0.f; g_deg_out[i] = 0.f; g_cursor[i] = 0; }
    if (i < NGRAPHS * HID) g_hg[i] = 0.f;
    if (i < NGRAPHS) g_cnt[i] = 0.f;
}

// ---------------- degree histograms ----------------
__global__ __launch_bounds__(256) void degree_kernel(const int* __restrict__ src,
                                                     const int* __restrict__ dst) {
    int e = blockIdx.x * blockDim.x + threadIdx.x;
    if (e < NEDGES) {
        atomicAdd(&g_deg_out[src[e]], 1.0f);
        atomicAdd(&g_deg_in[dst[e]], 1.0f);
    }
}

// ---------------- norms ----------------
__global__ __launch_bounds__(256) void norm_kernel() {
    int i = blockIdx.x * blockDim.x + threadIdx.x;
    if (i < NNODES) {
        g_norm_src[i] = rsqrtf(fmaxf(g_deg_out[i], 1.0f));
        g_norm_dst[i] = rsqrtf(fmaxf(g_deg_in[i], 1.0f));
    }
}

// ---------------- exclusive prefix scan of in-degrees (single block) ----------
__global__ __launch_bounds__(1024) void prefix_kernel() {
    __shared__ int wsum[32];
    __shared__ int s_base;
    int t = threadIdx.x, lane = t & 31, wid = t >> 5;
    if (t == 0) s_base = 0;
    __syncthreads();
    for (int base = 0; base < NNODES; base += 1024) {
        int i = base + t;
        int v = (i < NNODES) ? (int)g_deg_in[i] : 0;
        int x = v;
#pragma unroll
        for (int o = 1; o < 32; o <<= 1) { int y = __shfl_up_sync(~0u, x, o); if (lane >= o) x += y; }
        if (lane == 31) wsum[wid] = x;
        __syncthreads();
        if (wid == 0) {
            int w = wsum[lane];
#pragma unroll
            for (int o = 1; o < 32; o <<= 1) { int y = __shfl_up_sync(~0u, w, o); if (lane >= o) w += y; }
            wsum[lane] = w;
        }
        __syncthreads();
        int incl = x + (wid ? wsum[wid - 1] : 0) + s_base;
        if (i < NNODES) g_off[i] = incl - v;
        if (i == NNODES - 1) g_off[NNODES] = incl;
        __syncthreads();
        if (t == 0) s_base += wsum[31];
        __syncthreads();
    }
}

// ---------------- CSR fill: slot per edge under its dst ----------------
__global__ __launch_bounds__(256) void fill_kernel(const int* __restrict__ src,
                                                   const int* __restrict__ dst) {
    int e = blockIdx.x * blockDim.x + threadIdx.x;
    if (e < NEDGES) {
        int d = dst[e];
        int p = atomicAdd(&g_cursor[d], 1);
        g_eidx[g_off[d] + p] = src[e];
    }
}

// ---------------- layer 0: gather scalar + dense, fused; one warp per node ----
__global__ __launch_bounds__(256) void gather0_dense_kernel(const float* __restrict__ W0,
                                                            const float* __restrict__ b0) {
    int node = (blockIdx.x * blockDim.x + threadIdx.x) >> 5;
    int lane = threadIdx.x & 31;
    if (node >= NNODES) return;
    int beg = g_off[node], end = g_off[node + 1];
    float a = 0.f;
    for (int j = beg + lane; j < end; j += 32) {
        int s = g_eidx[j];
        a += g_deg_in[s] * g_norm_src[s];
    }
#pragma unroll
    for (int o = 16; o; o >>= 1) a += __shfl_xor_sync(~0u, a, o);
    a *= g_norm_dst[node];
    float ns = g_norm_src[node];
    float4 w = __ldg(&((const float4*)W0)[lane]);
    float4 b = __ldg(&((const float4*)b0)[lane]);
    float4 r;
    r.x = fmaxf(a * w.x + b.x, 0.f) * ns;
    r.y = fmaxf(a * w.y + b.y, 0.f) * ns;
    r.z = fmaxf(a * w.z + b.z, 0.f) * ns;
    r.w = fmaxf(a * w.w + b.w, 0.f) * ns;
    ((float4*)(g_ha + (size_t)node * HID))[lane] = r;
}

// ---------------- CSR gather: one warp per node, lane owns one float4 ---------
template <int PHASE>
__global__ __launch_bounds__(256) void gather_kernel() {
    const float4* __restrict__ h = (const float4*)(PHASE == 0 ? g_ha : g_hb);
    float4* __restrict__ agg = (float4*)(PHASE == 0 ? g_aggA : g_aggB);
    int node = (blockIdx.x * blockDim.x + threadIdx.x) >> 5;
    int lane = threadIdx.x & 31;
    if (node >= NNODES) return;
    int beg = g_off[node], end = g_off[node + 1];
    float4 a = make_float4(0.f, 0.f, 0.f, 0.f);
    for (int j = beg; j < end; j += 32) {
        int n = end - j;
        int myidx = (lane < n) ? __ldg(&g_eidx[j + lane]) : 0;
        int cnt = n < 32 ? n : 32;
        for (int k = 0; k < cnt; k++) {
            int s = __shfl_sync(~0u, myidx, k);
            float4 v = __ldg(&h[(size_t)s * 32 + lane]);
            a.x += v.x; a.y += v.y; a.z += v.z; a.w += v.w;
        }
    }
    agg[(size_t)node * 32 + lane] = a;
}

// ---------------- GEMM: out = relu((agg*norm_dst) @ W + b) [*norm_src] ----------
template <int PHASE>
__global__ __launch_bounds__(256) void gemm_relu_kernel(const float* __restrict__ W,
                                                        const float* __restrict__ bias) {
    const float* __restrict__ A = (PHASE == 0) ? g_aggA : g_aggB;
    float* __restrict__ O = (PHASE == 0) ? g_hb : g_ha;

    __shared__ float Ws[32 * HID];      // [kk][c]
    __shared__ float As[64 * 33];       // [r][kk], padded

    int t = threadIdx.x;
    int cg = t & 15;
    int rg = t >> 4;
    int row0 = blockIdx.x * 64;

    float acc[4][8];
#pragma unroll
    for (int r = 0; r < 4; r++)
#pragma unroll
        for (int j = 0; j < 8; j++) acc[r][j] = 0.f;

    for (int k0 = 0; k0 < HID; k0 += 32) {
#pragma unroll
        for (int i = 0; i < 16; i++) {
            int idx = t + i * 256;
            Ws[idx] = W[(size_t)(k0 + (idx >> 7)) * HID + (idx & 127)];
        }
#pragma unroll
        for (int i = 0; i < 8; i++) {
            int idx = t + i * 256;
            int r = idx >> 5, kk = idx & 31;
            int row = row0 + r;
            float v = 0.f;
            if (row < NNODES) v = A[(size_t)row * HID + k0 + kk] * g_norm_dst[row];
            As[r * 33 + kk] = v;
        }
        __syncthreads();
#pragma unroll
        for (int kk = 0; kk < 32; kk++) {
            float a0 = As[(rg * 4 + 0) * 33 + kk];
            float a1 = As[(rg * 4 + 1) * 33 + kk];
            float a2 = As[(rg * 4 + 2) * 33 + kk];
            float a3 = As[(rg * 4 + 3) * 33 + kk];
            float4 w0 = *(const float4*)&Ws[kk * HID + cg * 8];
            float4 w1 = *(const float4*)&Ws[kk * HID + cg * 8 + 4];
            float w[8] = {w0.x, w0.y, w0.z, w0.w, w1.x, w1.y, w1.z, w1.w};
#pragma unroll
            for (int j = 0; j < 8; j++) {
                acc[0][j] += a0 * w[j];
                acc[1][j] += a1 * w[j];
                acc[2][j] += a2 * w[j];
                acc[3][j] += a3 * w[j];
            }
        }
        __syncthreads();
    }
#pragma unroll
    for (int r = 0; r < 4; r++) {
        int row = row0 + rg * 4 + r;
        if (row < NNODES) {
            float sc = (PHASE == 0) ? g_norm_src[row] : 1.0f;
#pragma unroll
            for (int j = 0; j < 8; j++) {
                int c = cg * 8 + j;
                O[(size_t)row * HID + c] = fmaxf(acc[r][j] + __ldg(&bias[c]), 0.0f) * sc;
            }
        }
    }
}

// ---------------- pooling: segmented sum, graph_ids sorted, float4 lanes ------
__global__ __launch_bounds__(128) void pool_kernel(const int* __restrict__ gid) {
    const float4* __restrict__ h4 = (const float4*)g_ha;
    int q = threadIdx.x & 31;
    int sub = threadIdx.x >> 5;
    int n0 = blockIdx.x * 64 + sub * 16;
    int nend = n0 + 16;
    if (nend > NNODES) nend = NNODES;
    if (n0 >= NNODES) return;
    float4 acc = make_float4(0.f, 0.f, 0.f, 0.f);
    int cacc = 0;
    int cur = __ldg(&gid[n0]);
    for (int n = n0; n < nend; n++) {
        int g = __ldg(&gid[n]);
        if (g != cur) {
            red_add_v4(&g_hg[cur * HID + q * 4], acc);
            if (q == 0) atomicAdd(&g_cnt[cur], (float)cacc);
            acc = make_float4(0.f, 0.f, 0.f, 0.f); cacc = 0; cur = g;
        }
        float4 v = h4[(size_t)n * 32 + q];
        acc.x += v.x; acc.y += v.y; acc.z += v.z; acc.w += v.w;
        cacc++;
    }
    red_add_v4(&g_hg[cur * HID + q * 4], acc);
    if (q == 0) atomicAdd(&g_cnt[cur], (float)cacc);
}

// ---------------- classifier: out = (hg/cnt) @ Wc + bc ----------------
__global__ __launch_bounds__(256) void cls_kernel(const float* __restrict__ Wc,
                                                  const float* __restrict__ bc,
                                                  float* __restrict__ out) {
    int g = blockIdx.x * (blockDim.x >> 5) + (threadIdx.x >> 5);
    int lane = threadIdx.x & 31;
    if (g >= NGRAPHS) return;
    float inv = 1.0f / fmaxf(g_cnt[g], 1.0f);
    float x[4];
#pragma unroll
    for (int j = 0; j < 4; j++) x[j] = g_hg[g * HID + lane + j * 32] * inv;
#pragma unroll
    for (int cls = 0; cls < NCLS; cls++) {
        float p = 0.f;
#pragma unroll
        for (int j = 0; j < 4; j++) p += x[j] * __ldg(&Wc[(lane + j * 32) * NCLS + cls]);
#pragma unroll
        for (int o = 16; o; o >>= 1) p += __shfl_xor_sync(0xffffffffu, p, o);
        if (lane == 0) out[g * NCLS + cls] = p + __ldg(&bc[cls]);
    }
}

// ---------------- launch ----------------
extern "C" void kernel_launch(void* const* d_in, const int* in_sizes, int n_in,
                              void* d_out, int out_size) {
    const float* W0 = (const float*)d_in[0];
    const float* b0 = (const float*)d_in[1];
    const float* W1 = (const float*)d_in[2];
    const float* b1 = (const float*)d_in[3];
    const float* W2 = (const float*)d_in[4];
    const float* b2 = (const float*)d_in[5];
    const float* Wc = (const float*)d_in[6];
    const float* bc = (const float*)d_in[7];
    const int* src = (const int*)d_in[8];
    const int* dst = (const int*)d_in[9];
    const int* gid = (const int*)d_in[10];
    float* out = (float*)d_out;

    const int EB = (NEDGES + 255) / 256;
    const int NB = (NNODES + 255) / 256;
    const int ZB = (NGRAPHS * HID + 255) / 256;  // 256 blocks: covers hg AND nodes
    const int WB = (NNODES * 32 + 255) / 256;    // one warp per node
    const int GB = (NNODES + 63) / 64;

    zero_kernel<<<ZB, 256>>>();
    degree_kernel<<<EB, 256>>>(src, dst);
    norm_kernel<<<NB, 256>>>();
    prefix_kernel<<<1, 1024>>>();
    fill_kernel<<<EB, 256>>>(src, dst);

    gather0_dense_kernel<<<WB, 256>>>(W0, b0);

    gather_kernel<0><<<WB, 256>>>();
    gemm_relu_kernel<0><<<GB, 256>>>(W1, b1);

    gather_kernel<1><<<WB, 256>>>();
    gemm_relu_kernel<1><<<GB, 256>>>(W2, b2);

    pool_kernel<<<GB, 128>>>(gid);
    cls_kernel<<<(NGRAPHS + 7) / 8, 256>>>(Wc, bc, out);
}

// round 7
// speedup vs baseline: 1.4322x; 1.1033x over previous
#include <cuda_runtime.h>
#include <cuda_bf16.h>

#define NNODES 50000
#define NEDGES 800000
#define NGRAPHS 512
#define HID 128
#define NCLS 10
#define SCAN_B ((NNODES + 255) / 256)   // 196 scan blocks

// ---------------- scratch (device globals; no allocs allowed) ----------------
__device__ float g_deg_in[NNODES];
__device__ float g_deg_out[NNODES];
__device__ float g_norm_src[NNODES];
__device__ float g_norm_dst[NNODES];
__device__ float g_ha[(size_t)NNODES * HID];
__device__ float g_hb[(size_t)NNODES * HID];
__device__ float g_aggA[(size_t)NNODES * HID];
__device__ float g_aggB[(size_t)NNODES * HID];
__device__ float g_hg[NGRAPHS * HID];
__device__ float g_cnt[NGRAPHS];
// CSR by destination
__device__ int g_off[NNODES + 1];
__device__ int g_cursor[NNODES];
__device__ int g_eidx[NEDGES];
__device__ int g_bsum[SCAN_B];
__device__ int g_boff[SCAN_B];

__device__ __forceinline__ void red_add_v4(float* addr, float4 v) {
    asm volatile("red.global.add.v4.f32 [%0], {%1,%2,%3,%4};"
                 :: "l"(addr), "f"(v.x), "f"(v.y), "f"(v.z), "f"(v.w) : "memory");
}

// ---------------- zero all accumulated state ----------------
__global__ __launch_bounds__(256) void zero_kernel() {
    int i = blockIdx.x * blockDim.x + threadIdx.x;     // 0..65535
    if (i < NNODES) { g_deg_in[i] = 0.f; g_deg_out[i] = 0.f; g_cursor[i] = 0; }
    if (i < NGRAPHS * HID) g_hg[i] = 0.f;
    if (i < NGRAPHS) g_cnt[i] = 0.f;
}

// ---------------- degree histograms ----------------
__global__ __launch_bounds__(256) void degree_kernel(const int* __restrict__ src,
                                                     const int* __restrict__ dst) {
    int e = blockIdx.x * blockDim.x + threadIdx.x;
    if (e < NEDGES) {
        atomicAdd(&g_deg_out[src[e]], 1.0f);
        atomicAdd(&g_deg_in[dst[e]], 1.0f);
    }
}

// ---------------- norms ----------------
__global__ __launch_bounds__(256) void norm_kernel() {
    int i = blockIdx.x * blockDim.x + threadIdx.x;
    if (i < NNODES) {
        g_norm_src[i] = rsqrtf(fmaxf(g_deg_out[i], 1.0f));
        g_norm_dst[i] = rsqrtf(fmaxf(g_deg_in[i], 1.0f));
    }
}

// ---------------- scan stage A: per-block exclusive scan + block sums ---------
__global__ __launch_bounds__(256) void scan_a_kernel() {
    __shared__ int wsum[8];
    int t = threadIdx.x, lane = t & 31, wid = t >> 5;
    int i = blockIdx.x * 256 + t;
    int v = (i < NNODES) ? (int)g_deg_in[i] : 0;
    int x = v;
#pragma unroll
    for (int o = 1; o < 32; o <<= 1) { int y = __shfl_up_sync(~0u, x, o); if (lane >= o) x += y; }
    if (lane == 31) wsum[wid] = x;
    __syncthreads();
    if (wid == 0 && lane < 8) {
        int w = wsum[lane];
#pragma unroll
        for (int o = 1; o < 8; o <<= 1) { int y = __shfl_up_sync(0xffu, w, o); if (lane >= o) w += y; }
        wsum[lane] = w;
    }
    __syncthreads();
    int incl = x + (wid ? wsum[wid - 1] : 0);
    if (i < NNODES) g_off[i] = incl - v;
    if (t == 255) g_bsum[blockIdx.x] = incl;
}

// ---------------- scan stage B: scan the block sums (1 block) ----------------
__global__ __launch_bounds__(256) void scan_b_kernel() {
    __shared__ int wsum[8];
    int t = threadIdx.x, lane = t & 31, wid = t >> 5;
    int v = (t < SCAN_B) ? g_bsum[t] : 0;
    int x = v;
#pragma unroll
    for (int o = 1; o < 32; o <<= 1) { int y = __shfl_up_sync(~0u, x, o); if (lane >= o) x += y; }
    if (lane == 31) wsum[wid] = x;
    __syncthreads();
    if (wid == 0 && lane < 8) {
        int w = wsum[lane];
#pragma unroll
        for (int o = 1; o < 8; o <<= 1) { int y = __shfl_up_sync(0xffu, w, o); if (lane >= o) w += y; }
        wsum[lane] = w;
    }
    __syncthreads();
    int incl = x + (wid ? wsum[wid - 1] : 0);
    if (t < SCAN_B) g_boff[t] = incl - v;
    if (t == SCAN_B - 1) g_off[NNODES] = incl;
}

// ---------------- scan stage C: add block offsets ----------------
__global__ __launch_bounds__(256) void scan_c_kernel() {
    int i = blockIdx.x * 256 + threadIdx.x;
    if (i < NNODES && blockIdx.x > 0) g_off[i] += g_boff[blockIdx.x];
}

// ---------------- CSR fill: slot per edge under its dst ----------------
__global__ __launch_bounds__(256) void fill_kernel(const int* __restrict__ src,
                                                   const int* __restrict__ dst) {
    int e = blockIdx.x * blockDim.x + threadIdx.x;
    if (e < NEDGES) {
        int d = dst[e];
        int p = atomicAdd(&g_cursor[d], 1);
        g_eidx[g_off[d] + p] = src[e];
    }
}

// ---------------- layer 0: gather scalar + dense, fused; one warp per node ----
__global__ __launch_bounds__(256) void gather0_dense_kernel(const float* __restrict__ W0,
                                                            const float* __restrict__ b0) {
    int node = (blockIdx.x * blockDim.x + threadIdx.x) >> 5;
    int lane = threadIdx.x & 31;
    if (node >= NNODES) return;
    int beg = g_off[node], end = g_off[node + 1];
    float a = 0.f;
    for (int j = beg + lane; j < end; j += 32) {
        int s = g_eidx[j];
        a += g_deg_in[s] * g_norm_src[s];
    }
#pragma unroll
    for (int o = 16; o; o >>= 1) a += __shfl_xor_sync(~0u, a, o);
    a *= g_norm_dst[node];
    float ns = g_norm_src[node];
    float4 w = __ldg(&((const float4*)W0)[lane]);
    float4 b = __ldg(&((const float4*)b0)[lane]);
    float4 r;
    r.x = fmaxf(a * w.x + b.x, 0.f) * ns;
    r.y = fmaxf(a * w.y + b.y, 0.f) * ns;
    r.z = fmaxf(a * w.z + b.z, 0.f) * ns;
    r.w = fmaxf(a * w.w + b.w, 0.f) * ns;
    ((float4*)(g_ha + (size_t)node * HID))[lane] = r;
}

// ---------------- CSR gather: one warp per node, lane owns one float4 ---------
// Two independent edge loads per inner step for MLP.
template <int PHASE>
__global__ __launch_bounds__(256) void gather_kernel() {
    const float4* __restrict__ h = (const float4*)(PHASE == 0 ? g_ha : g_hb);
    float4* __restrict__ agg = (float4*)(PHASE == 0 ? g_aggA : g_aggB);
    int node = (blockIdx.x * blockDim.x + threadIdx.x) >> 5;
    int lane = threadIdx.x & 31;
    if (node >= NNODES) return;
    int beg = g_off[node], end = g_off[node + 1];
    float4 a0 = make_float4(0.f, 0.f, 0.f, 0.f);
    float4 a1 = make_float4(0.f, 0.f, 0.f, 0.f);
    for (int j = beg; j < end; j += 32) {
        int n = end - j;
        int myidx = (lane < n) ? __ldg(&g_eidx[j + lane]) : 0;
        int cnt = n < 32 ? n : 32;
        int k = 0;
        for (; k + 1 < cnt; k += 2) {
            int s0 = __shfl_sync(~0u, myidx, k);
            int s1 = __shfl_sync(~0u, myidx, k + 1);
            float4 v0 = __ldg(&h[(size_t)s0 * 32 + lane]);
            float4 v1 = __ldg(&h[(size_t)s1 * 32 + lane]);
            a0.x += v0.x; a0.y += v0.y; a0.z += v0.z; a0.w += v0.w;
            a1.x += v1.x; a1.y += v1.y; a1.z += v1.z; a1.w += v1.w;
        }
        if (k < cnt) {
            int s0 = __shfl_sync(~0u, myidx, k);
            float4 v0 = __ldg(&h[(size_t)s0 * 32 + lane]);
            a0.x += v0.x; a0.y += v0.y; a0.z += v0.z; a0.w += v0.w;
        }
    }
    a0.x += a1.x; a0.y += a1.y; a0.z += a1.z; a0.w += a1.w;
    agg[(size_t)node * 32 + lane] = a0;
}

// ---------------- GEMM: out = relu((agg*norm_dst) @ W + b) [*norm_src] ----------
template <int PHASE>
__global__ __launch_bounds__(256) void gemm_relu_kernel(const float* __restrict__ W,
                                                        const float* __restrict__ bias) {
    const float* __restrict__ A = (PHASE == 0) ? g_aggA : g_aggB;
    float* __restrict__ O = (PHASE == 0) ? g_hb : g_ha;

    __shared__ float Ws[32 * HID];
    __shared__ float As[64 * 33];

    int t = threadIdx.x;
    int cg = t & 15;
    int rg = t >> 4;
    int row0 = blockIdx.x * 64;

    float acc[4][8];
#pragma unroll
    for (int r = 0; r < 4; r++)
#pragma unroll
        for (int j = 0; j < 8; j++) acc[r][j] = 0.f;

    for (int k0 = 0; k0 < HID; k0 += 32) {
#pragma unroll
        for (int i = 0; i < 16; i++) {
            int idx = t + i * 256;
            Ws[idx] = W[(size_t)(k0 + (idx >> 7)) * HID + (idx & 127)];
        }
#pragma unroll
        for (int i = 0; i < 8; i++) {
            int idx = t + i * 256;
            int r = idx >> 5, kk = idx & 31;
            int row = row0 + r;
            float v = 0.f;
            if (row < NNODES) v = A[(size_t)row * HID + k0 + kk] * g_norm_dst[row];
            As[r * 33 + kk] = v;
        }
        __syncthreads();
#pragma unroll
        for (int kk = 0; kk < 32; kk++) {
            float a0 = As[(rg * 4 + 0) * 33 + kk];
            float a1 = As[(rg * 4 + 1) * 33 + kk];
            float a2 = As[(rg * 4 + 2) * 33 + kk];
            float a3 = As[(rg * 4 + 3) * 33 + kk];
            float4 w0 = *(const float4*)&Ws[kk * HID + cg * 8];
            float4 w1 = *(const float4*)&Ws[kk * HID + cg * 8 + 4];
            float w[8] = {w0.x, w0.y, w0.z, w0.w, w1.x, w1.y, w1.z, w1.w};
#pragma unroll
            for (int j = 0; j < 8; j++) {
                acc[0][j] += a0 * w[j];
                acc[1][j] += a1 * w[j];
                acc[2][j] += a2 * w[j];
                acc[3][j] += a3 * w[j];
            }
        }
        __syncthreads();
    }
#pragma unroll
    for (int r = 0; r < 4; r++) {
        int row = row0 + rg * 4 + r;
        if (row < NNODES) {
            float sc = (PHASE == 0) ? g_norm_src[row] : 1.0f;
#pragma unroll
            for (int j = 0; j < 8; j++) {
                int c = cg * 8 + j;
                O[(size_t)row * HID + c] = fmaxf(acc[r][j] + __ldg(&bias[c]), 0.0f) * sc;
            }
        }
    }
}

// ---------------- pooling: segmented sum, graph_ids sorted, float4 lanes ------
__global__ __launch_bounds__(128) void pool_kernel(const int* __restrict__ gid) {
    const float4* __restrict__ h4 = (const float4*)g_ha;
    int q = threadIdx.x & 31;
    int sub = threadIdx.x >> 5;
    int n0 = blockIdx.x * 64 + sub * 16;
    int nend = n0 + 16;
    if (nend > NNODES) nend = NNODES;
    if (n0 >= NNODES) return;
    float4 acc = make_float4(0.f, 0.f, 0.f, 0.f);
    int cacc = 0;
    int cur = __ldg(&gid[n0]);
    for (int n = n0; n < nend; n++) {
        int g = __ldg(&gid[n]);
        if (g != cur) {
            red_add_v4(&g_hg[cur * HID + q * 4], acc);
            if (q == 0) atomicAdd(&g_cnt[cur], (float)cacc);
            acc = make_float4(0.f, 0.f, 0.f, 0.f); cacc = 0; cur = g;
        }
        float4 v = h4[(size_t)n * 32 + q];
        acc.x += v.x; acc.y += v.y; acc.z += v.z; acc.w += v.w;
        cacc++;
    }
    red_add_v4(&g_hg[cur * HID + q * 4], acc);
    if (q == 0) atomicAdd(&g_cnt[cur], (float)cacc);
}

// ---------------- classifier: out = (hg/cnt) @ Wc + bc ----------------
__global__ __launch_bounds__(256) void cls_kernel(const float* __restrict__ Wc,
                                                  const float* __restrict__ bc,
                                                  float* __restrict__ out) {
    int g = blockIdx.x * (blockDim.x >> 5) + (threadIdx.x >> 5);
    int lane = threadIdx.x & 31;
    if (g >= NGRAPHS) return;
    float inv = 1.0f / fmaxf(g_cnt[g], 1.0f);
    float x[4];
#pragma unroll
    for (int j = 0; j < 4; j++) x[j] = g_hg[g * HID + lane + j * 32] * inv;
#pragma unroll
    for (int cls = 0; cls < NCLS; cls++) {
        float p = 0.f;
#pragma unroll
        for (int j = 0; j < 4; j++) p += x[j] * __ldg(&Wc[(lane + j * 32) * NCLS + cls]);
#pragma unroll
        for (int o = 16; o; o >>= 1) p += __shfl_xor_sync(0xffffffffu, p, o);
        if (lane == 0) out[g * NCLS + cls] = p + __ldg(&bc[cls]);
    }
}

// ---------------- launch ----------------
extern "C" void kernel_launch(void* const* d_in, const int* in_sizes, int n_in,
                              void* d_out, int out_size) {
    const float* W0 = (const float*)d_in[0];
    const float* b0 = (const float*)d_in[1];
    const float* W1 = (const float*)d_in[2];
    const float* b1 = (const float*)d_in[3];
    const float* W2 = (const float*)d_in[4];
    const float* b2 = (const float*)d_in[5];
    const float* Wc = (const float*)d_in[6];
    const float* bc = (const float*)d_in[7];
    const int* src = (const int*)d_in[8];
    const int* dst = (const int*)d_in[9];
    const int* gid = (const int*)d_in[10];
    float* out = (float*)d_out;

    const int EB = (NEDGES + 255) / 256;
    const int NB = (NNODES + 255) / 256;       // == SCAN_B
    const int ZB = (NGRAPHS * HID + 255) / 256;
    const int WB = (NNODES * 32 + 255) / 256;
    const int GB = (NNODES + 63) / 64;

    zero_kernel<<<ZB, 256>>>();
    degree_kernel<<<EB, 256>>>(src, dst);
    norm_kernel<<<NB, 256>>>();
    scan_a_kernel<<<SCAN_B, 256>>>();
    scan_b_kernel<<<1, 256>>>();
    scan_c_kernel<<<SCAN_B, 256>>>();
    fill_kernel<<<EB, 256>>>(src, dst);

    gather0_dense_kernel<<<WB, 256>>>(W0, b0);

    gather_kernel<0><<<WB, 256>>>();
    gemm_relu_kernel<0><<<GB, 256>>>(W1, b1);

    gather_kernel<1><<<WB, 256>>>();
    gemm_relu_kernel<1><<<GB, 256>>>(W2, b2);

    pool_kernel<<<GB, 128>>>(gid);
    cls_kernel<<<(NGRAPHS + 7) / 8, 256>>>(Wc, bc, out);
}

// round 9
// speedup vs baseline: 1.6217x; 1.1323x over previous
#include <cuda_runtime.h>
#include <cuda_bf16.h>
#include <cstdint>

#define NNODES 50000
#define NEDGES 800000
#define NGRAPHS 512
#define HID 128
#define NCLS 10
#define SCAN_B ((NNODES + 255) / 256)   // 196 scan blocks

// ---------------- scratch (device globals; no allocs allowed) ----------------
__device__ float g_deg_in[NNODES];
__device__ float g_deg_out[NNODES];
__device__ float g_norm_src[NNODES];
__device__ float g_norm_dst[NNODES];
__device__ float g_ha[(size_t)NNODES * HID];
__device__ float g_hb[(size_t)NNODES * HID];
__device__ float g_aggA[(size_t)NNODES * HID];
__device__ float g_aggB[(size_t)NNODES * HID];
__device__ float g_hg[NGRAPHS * HID];
__device__ float g_cnt[NGRAPHS];
// CSR by destination
__device__ int g_off[NNODES + 1];
__device__ int g_cursor[NNODES];
__device__ int g_eidx[NEDGES];
__device__ int g_bsum[SCAN_B];
__device__ int g_boff[SCAN_B];

__device__ __forceinline__ void red_add_v4(float* addr, float4 v) {
    asm volatile("red.global.add.v4.f32 [%0], {%1,%2,%3,%4};"
                 :: "l"(addr), "f"(v.x), "f"(v.y), "f"(v.z), "f"(v.w) : "memory");
}

__device__ __forceinline__ uint32_t f32_to_tf32(float v) {
    uint32_t r;
    asm("cvt.rna.tf32.f32 %0, %1;" : "=r"(r) : "f"(v));
    return r;
}

__device__ __forceinline__ void mma_tf32(float d[4], const uint32_t a[4],
                                         uint32_t b0, uint32_t b1) {
    asm volatile("mma.sync.aligned.m16n8k8.row.col.f32.tf32.tf32.f32 "
                 "{%0,%1,%2,%3}, {%4,%5,%6,%7}, {%8,%9}, {%0,%1,%2,%3};"
                 : "+f"(d[0]), "+f"(d[1]), "+f"(d[2]), "+f"(d[3])
                 : "r"(a[0]), "r"(a[1]), "r"(a[2]), "r"(a[3]), "r"(b0), "r"(b1));
}

// ---------------- zero all accumulated state ----------------
__global__ __launch_bounds__(256) void zero_kernel() {
    int i = blockIdx.x * blockDim.x + threadIdx.x;     // 0..65535
    if (i < NNODES) { g_deg_in[i] = 0.f; g_deg_out[i] = 0.f; g_cursor[i] = 0; }
    if (i < NGRAPHS * HID) g_hg[i] = 0.f;
    if (i < NGRAPHS) g_cnt[i] = 0.f;
}

// ---------------- degree histograms ----------------
__global__ __launch_bounds__(256) void degree_kernel(const int* __restrict__ src,
                                                     const int* __restrict__ dst) {
    int e = blockIdx.x * blockDim.x + threadIdx.x;
    if (e < NEDGES) {
        atomicAdd(&g_deg_out[src[e]], 1.0f);
        atomicAdd(&g_deg_in[dst[e]], 1.0f);
    }
}

// ---------------- norms ----------------
__global__ __launch_bounds__(256) void norm_kernel() {
    int i = blockIdx.x * blockDim.x + threadIdx.x;
    if (i < NNODES) {
        g_norm_src[i] = rsqrtf(fmaxf(g_deg_out[i], 1.0f));
        g_norm_dst[i] = rsqrtf(fmaxf(g_deg_in[i], 1.0f));
    }
}

// ---------------- scan stage A: per-block exclusive scan + block sums ---------
__global__ __launch_bounds__(256) void scan_a_kernel() {
    __shared__ int wsum[8];
    int t = threadIdx.x, lane = t & 31, wid = t >> 5;
    int i = blockIdx.x * 256 + t;
    int v = (i < NNODES) ? (int)g_deg_in[i] : 0;
    int x = v;
#pragma unroll
    for (int o = 1; o < 32; o <<= 1) { int y = __shfl_up_sync(~0u, x, o); if (lane >= o) x += y; }
    if (lane == 31) wsum[wid] = x;
    __syncthreads();
    if (wid == 0 && lane < 8) {
        int w = wsum[lane];
#pragma unroll
        for (int o = 1; o < 8; o <<= 1) { int y = __shfl_up_sync(0xffu, w, o); if (lane >= o) w += y; }
        wsum[lane] = w;
    }
    __syncthreads();
    int incl = x + (wid ? wsum[wid - 1] : 0);
    if (i < NNODES) g_off[i] = incl - v;
    if (t == 255) g_bsum[blockIdx.x] = incl;
}

// ---------------- scan stage B: scan the block sums (1 block) ----------------
__global__ __launch_bounds__(256) void scan_b_kernel() {
    __shared__ int wsum[8];
    int t = threadIdx.x, lane = t & 31, wid = t >> 5;
    int v = (t < SCAN_B) ? g_bsum[t] : 0;
    int x = v;
#pragma unroll
    for (int o = 1; o < 32; o <<= 1) { int y = __shfl_up_sync(~0u, x, o); if (lane >= o) x += y; }
    if (lane == 31) wsum[wid] = x;
    __syncthreads();
    if (wid == 0 && lane < 8) {
        int w = wsum[lane];
#pragma unroll
        for (int o = 1; o < 8; o <<= 1) { int y = __shfl_up_sync(0xffu, w, o); if (lane >= o) w += y; }
        wsum[lane] = w;
    }
    __syncthreads();
    int incl = x + (wid ? wsum[wid - 1] : 0);
    if (t < SCAN_B) g_boff[t] = incl - v;
    if (t == SCAN_B - 1) g_off[NNODES] = incl;
}

// ---------------- scan stage C: add block offsets ----------------
__global__ __launch_bounds__(256) void scan_c_kernel() {
    int i = blockIdx.x * 256 + threadIdx.x;
    if (i < NNODES && blockIdx.x > 0) g_off[i] += g_boff[blockIdx.x];
}

// ---------------- CSR fill: slot per edge under its dst ----------------
__global__ __launch_bounds__(256) void fill_kernel(const int* __restrict__ src,
                                                   const int* __restrict__ dst) {
    int e = blockIdx.x * blockDim.x + threadIdx.x;
    if (e < NEDGES) {
        int d = dst[e];
        int p = atomicAdd(&g_cursor[d], 1);
        g_eidx[g_off[d] + p] = src[e];
    }
}

// ---------------- layer 0: gather scalar + dense, fused; one warp per node ----
__global__ __launch_bounds__(256) void gather0_dense_kernel(const float* __restrict__ W0,
                                                            const float* __restrict__ b0) {
    int node = (blockIdx.x * blockDim.x + threadIdx.x) >> 5;
    int lane = threadIdx.x & 31;
    if (node >= NNODES) return;
    int beg = g_off[node], end = g_off[node + 1];
    float a = 0.f;
    for (int j = beg + lane; j < end; j += 32) {
        int s = g_eidx[j];
        a += g_deg_in[s] * g_norm_src[s];
    }
#pragma unroll
    for (int o = 16; o; o >>= 1) a += __shfl_xor_sync(~0u, a, o);
    a *= g_norm_dst[node];
    float ns = g_norm_src[node];
    float4 w = __ldg(&((const float4*)W0)[lane]);
    float4 b = __ldg(&((const float4*)b0)[lane]);
    float4 r;
    r.x = fmaxf(a * w.x + b.x, 0.f) * ns;
    r.y = fmaxf(a * w.y + b.y, 0.f) * ns;
    r.z = fmaxf(a * w.z + b.z, 0.f) * ns;
    r.w = fmaxf(a * w.w + b.w, 0.f) * ns;
    ((float4*)(g_ha + (size_t)node * HID))[lane] = r;
}

// ---------------- CSR gather: one warp per node, lane owns one float4 ---------
template <int PHASE>
__global__ __launch_bounds__(256) void gather_kernel() {
    const float4* __restrict__ h = (const float4*)(PHASE == 0 ? g_ha : g_hb);
    float4* __restrict__ agg = (float4*)(PHASE == 0 ? g_aggA : g_aggB);
    int node = (blockIdx.x * blockDim.x + threadIdx.x) >> 5;
    int lane = threadIdx.x & 31;
    if (node >= NNODES) return;
    int beg = g_off[node], end = g_off[node + 1];
    float4 a0 = make_float4(0.f, 0.f, 0.f, 0.f);
    float4 a1 = make_float4(0.f, 0.f, 0.f, 0.f);
    for (int j = beg; j < end; j += 32) {
        int n = end - j;
        int myidx = (lane < n) ? __ldg(&g_eidx[j + lane]) : 0;
        int cnt = n < 32 ? n : 32;
        int k = 0;
        for (; k + 1 < cnt; k += 2) {
            int s0 = __shfl_sync(~0u, myidx, k);
            int s1 = __shfl_sync(~0u, myidx, k + 1);
            float4 v0 = __ldg(&h[(size_t)s0 * 32 + lane]);
            float4 v1 = __ldg(&h[(size_t)s1 * 32 + lane]);
            a0.x += v0.x; a0.y += v0.y; a0.z += v0.z; a0.w += v0.w;
            a1.x += v1.x; a1.y += v1.y; a1.z += v1.z; a1.w += v1.w;
        }
        if (k < cnt) {
            int s0 = __shfl_sync(~0u, myidx, k);
            float4 v0 = __ldg(&h[(size_t)s0 * 32 + lane]);
            a0.x += v0.x; a0.y += v0.y; a0.z += v0.z; a0.w += v0.w;
        }
    }
    a0.x += a1.x; a0.y += a1.y; a0.z += a1.z; a0.w += a1.w;
    agg[(size_t)node * 32 + lane] = a0;
}

// ---------------- GEMM via 3xTF32 mma.sync -------------------------------------
// out = relu((agg*norm_dst) @ W + b) [*norm_src if PHASE==0]
// Block: 64 rows x 128 cols, 8 warps; warp w -> rows (w>>1)*16.., cols (w&1)*64..
template <int PHASE>
__global__ __launch_bounds__(256) void gemm_tf32_kernel(const float* __restrict__ W,
                                                        const float* __restrict__ bias) {
    const float* __restrict__ A = (PHASE == 0) ? g_aggA : g_aggB;
    float* __restrict__ O = (PHASE == 0) ? g_hb : g_ha;

    __shared__ float As[64][36];       // fp32 A chunk (conflict-free: 4*gid+tig)
    __shared__ float Wh[32][136];      // tf32-hi of W chunk (conflict-free: 8*tig+gid)
    __shared__ float Wl[32][136];      // tf32-lo of W chunk

    int t = threadIdx.x;
    int w = t >> 5, lane = t & 31;
    int gid = lane >> 2, tig = lane & 3;
    int m_base = (w >> 1) * 16;        // 0,16,32,48
    int n_base = (w & 1) * 64;         // 0,64
    int row0 = blockIdx.x * 64;

    float d[8][4];
#pragma unroll
    for (int nt = 0; nt < 8; nt++)
#pragma unroll
        for (int i = 0; i < 4; i++) d[nt][i] = 0.f;

    for (int k0 = 0; k0 < HID; k0 += 32) {
        // stage W chunk hi/lo: 32x128
#pragma unroll
        for (int i = 0; i < 16; i++) {
            int idx = t + i * 256;
            int r = idx >> 7, c = idx & 127;
            float v = W[(size_t)(k0 + r) * HID + c];
            uint32_t hb = f32_to_tf32(v);
            float hf = __uint_as_float(hb);
            uint32_t lb = f32_to_tf32(v - hf);
            Wh[r][c] = hf;
            Wl[r][c] = __uint_as_float(lb);
        }
        // stage A chunk (scaled by norm_dst): 64 rows x 32
#pragma unroll
        for (int i = 0; i < 8; i++) {
            int idx = t + i * 256;
            int r = idx >> 5, kk = idx & 31;
            int row = row0 + r;
            float v = 0.f;
            if (row < NNODES) v = A[(size_t)row * HID + k0 + kk] * g_norm_dst[row];
            As[r][kk] = v;
        }
        __syncthreads();

#pragma unroll
        for (int ks = 0; ks < 4; ks++) {
            // A fragment (m16 x k8), hi/lo split
            uint32_t ah[4], al[4];
#pragma unroll
            for (int i = 0; i < 4; i++) {
                int r = m_base + gid + (i & 1) * 8;
                int kk = ks * 8 + tig + (i >> 1) * 4;
                float v = As[r][kk];
                uint32_t hb = f32_to_tf32(v);
                ah[i] = hb;
                al[i] = f32_to_tf32(v - __uint_as_float(hb));
            }
#pragma unroll
            for (int nt = 0; nt < 8; nt++) {
                int c = n_base + nt * 8 + gid;
                uint32_t bh0 = __float_as_uint(Wh[ks * 8 + tig][c]);
                uint32_t bh1 = __float_as_uint(Wh[ks * 8 + tig + 4][c]);
                uint32_t bl0 = __float_as_uint(Wl[ks * 8 + tig][c]);
                uint32_t bl1 = __float_as_uint(Wl[ks * 8 + tig + 4][c]);
                mma_tf32(d[nt], ah, bh0, bh1);
                mma_tf32(d[nt], al, bh0, bh1);
                mma_tf32(d[nt], ah, bl0, bl1);
            }
        }
        __syncthreads();
    }

    // epilogue: c layout (row gid / gid+8, col 2*tig / +1)
#pragma unroll
    for (int nt = 0; nt < 8; nt++) {
        int c0 = n_base + nt * 8 + 2 * tig;
#pragma unroll
        for (int i = 0; i < 4; i++) {
            int row = row0 + m_base + gid + (i >> 1) * 8;
            int col = c0 + (i & 1);
            if (row < NNODES) {
                float sc = (PHASE == 0) ? g_norm_src[row] : 1.0f;
                O[(size_t)row * HID + col] =
                    fmaxf(d[nt][i] + __ldg(&bias[col]), 0.0f) * sc;
            }
        }
    }
}

// ---------------- pooling: segmented sum, graph_ids sorted, float4 lanes ------
__global__ __launch_bounds__(128) void pool_kernel(const int* __restrict__ gid) {
    const float4* __restrict__ h4 = (const float4*)g_ha;
    int q = threadIdx.x & 31;
    int sub = threadIdx.x >> 5;
    int n0 = blockIdx.x * 64 + sub * 16;
    int nend = n0 + 16;
    if (nend > NNODES) nend = NNODES;
    if (n0 >= NNODES) return;
    float4 acc = make_float4(0.f, 0.f, 0.f, 0.f);
    int cacc = 0;
    int cur = __ldg(&gid[n0]);
    for (int n = n0; n < nend; n++) {
        int g = __ldg(&gid[n]);
        if (g != cur) {
            red_add_v4(&g_hg[cur * HID + q * 4], acc);
            if (q == 0) atomicAdd(&g_cnt[cur], (float)cacc);
            acc = make_float4(0.f, 0.f, 0.f, 0.f); cacc = 0; cur = g;
        }
        float4 v = h4[(size_t)n * 32 + q];
        acc.x += v.x; acc.y += v.y; acc.z += v.z; acc.w += v.w;
        cacc++;
    }
    red_add_v4(&g_hg[cur * HID + q * 4], acc);
    if (q == 0) atomicAdd(&g_cnt[cur], (float)cacc);
}

// ---------------- classifier: out = (hg/cnt) @ Wc + bc ----------------
__global__ __launch_bounds__(256) void cls_kernel(const float* __restrict__ Wc,
                                                  const float* __restrict__ bc,
                                                  float* __restrict__ out) {
    int g = blockIdx.x * (blockDim.x >> 5) + (threadIdx.x >> 5);
    int lane = threadIdx.x & 31;
    if (g >= NGRAPHS) return;
    float inv = 1.0f / fmaxf(g_cnt[g], 1.0f);
    float x[4];
#pragma unroll
    for (int j = 0; j < 4; j++) x[j] = g_hg[g * HID + lane + j * 32] * inv;
#pragma unroll
    for (int cls = 0; cls < NCLS; cls++) {
        float p = 0.f;
#pragma unroll
        for (int j = 0; j < 4; j++) p += x[j] * __ldg(&Wc[(lane + j * 32) * NCLS + cls]);
#pragma unroll
        for (int o = 16; o; o >>= 1) p += __shfl_xor_sync(0xffffffffu, p, o);
        if (lane == 0) out[g * NCLS + cls] = p + __ldg(&bc[cls]);
    }
}

// ---------------- launch ----------------
extern "C" void kernel_launch(void* const* d_in, const int* in_sizes, int n_in,
                              void* d_out, int out_size) {
    const float* W0 = (const float*)d_in[0];
    const float* b0 = (const float*)d_in[1];
    const float* W1 = (const float*)d_in[2];
    const float* b1 = (const float*)d_in[3];
    const float* W2 = (const float*)d_in[4];
    const float* b2 = (const float*)d_in[5];
    const float* Wc = (const float*)d_in[6];
    const float* bc = (const float*)d_in[7];
    const int* src = (const int*)d_in[8];
    const int* dst = (const int*)d_in[9];
    const int* gid = (const int*)d_in[10];
    float* out = (float*)d_out;

    const int EB = (NEDGES + 255) / 256;
    const int NB = (NNODES + 255) / 256;       // == SCAN_B
    const int ZB = (NGRAPHS * HID + 255) / 256;
    const int WB = (NNODES * 32 + 255) / 256;
    const int GB = (NNODES + 63) / 64;         // 782 (also GEMM grid)

    zero_kernel<<<ZB, 256>>>();
    degree_kernel<<<EB, 256>>>(src, dst);
    norm_kernel<<<NB, 256>>>();
    scan_a_kernel<<<SCAN_B, 256>>>();
    scan_b_kernel<<<1, 256>>>();
    scan_c_kernel<<<SCAN_B, 256>>>();
    fill_kernel<<<EB, 256>>>(src, dst);

    gather0_dense_kernel<<<WB, 256>>>(W0, b0);

    gather_kernel<0><<<WB, 256>>>();
    gemm_tf32_kernel<0><<<GB, 256>>>(W1, b1);

    gather_kernel<1><<<WB, 256>>>();
    gemm_tf32_kernel<1><<<GB, 256>>>(W2, b2);

    pool_kernel<<<GB, 128>>>(gid);
    cls_kernel<<<(NGRAPHS + 7) / 8, 256>>>(Wc, bc, out);
}